// round 1
// baseline (speedup 1.0000x reference)
#include <cuda_runtime.h>
#include <math.h>

#define N_NODES 50000
#define N_EDGES 800000
#define HEADS 8
#define ODIM 8
#define HID 64          // HEADS*ODIM
#define CLAMP_V 5.0f

// Scratch (static __device__ — no allocations allowed)
__device__ float g_Q[N_NODES * HID];
__device__ float g_K[N_NODES * HID];
__device__ float g_V[N_NODES * HID];
__device__ float g_s[N_NODES * HEADS];     // sum of exp(a) per (node, head)
__device__ float g_wV[N_NODES * HID];      // unnormalized sum p * V[src]
__device__ float g_row[N_NODES * HID];     // unnormalized sum p * e_t

__device__ __forceinline__ void red_add_v4(float* ptr, float a, float b, float c, float d) {
    asm volatile("red.global.add.v4.f32 [%0], {%1,%2,%3,%4};"
                 :: "l"(ptr), "f"(a), "f"(b), "f"(c), "f"(d) : "memory");
}

// ============================================================
// Kernel 1: Q/K/V = x @ [Wq|Wk|Wv] + bias.  64 rows per block,
// 256 threads, thread tile 8 rows x 6 cols over 192 cols.
// ============================================================
__global__ void qkv_kernel(const float* __restrict__ x,
                           const float* __restrict__ Wq, const float* __restrict__ bq,
                           const float* __restrict__ Wk, const float* __restrict__ bk,
                           const float* __restrict__ Wv, const float* __restrict__ bv) {
    extern __shared__ float sm[];
    float (*Ws)[192] = (float(*)[192])sm;                 // 64 x 192
    float (*xT)[65]  = (float(*)[65])(sm + 64 * 192);     // 64 x 65 (padded)

    const int tid = threadIdx.x;
    const int tr = tid >> 5;    // 0..7  -> rows tr*8 .. tr*8+7
    const int tc = tid & 31;    // 0..31 -> cols tc*6 .. tc*6+5
    const int row0 = blockIdx.x * 64;

    for (int i = tid; i < 64 * 64; i += 256) {
        int k = i >> 6, c = i & 63;
        Ws[k][c]       = Wq[i];
        Ws[k][c + 64]  = Wk[i];
        Ws[k][c + 128] = Wv[i];
    }
    for (int i = tid; i < 64 * 64; i += 256) {
        int r = i >> 6, k = i & 63;
        float v = (row0 + r < N_NODES) ? x[(size_t)(row0 + r) * 64 + k] : 0.f;
        xT[k][r] = v;
    }
    __syncthreads();

    float acc[8][6];
    #pragma unroll
    for (int j = 0; j < 6; j++) {
        int c = tc * 6 + j;
        float b = (c < 64) ? bq[c] : (c < 128 ? bk[c - 64] : bv[c - 128]);
        #pragma unroll
        for (int i = 0; i < 8; i++) acc[i][j] = b;
    }

    for (int k = 0; k < 64; k++) {
        float a[8], b[6];
        #pragma unroll
        for (int i = 0; i < 8; i++) a[i] = xT[k][tr * 8 + i];
        #pragma unroll
        for (int j = 0; j < 6; j++) b[j] = Ws[k][tc * 6 + j];
        #pragma unroll
        for (int i = 0; i < 8; i++)
            #pragma unroll
            for (int j = 0; j < 6; j++)
                acc[i][j] = fmaf(a[i], b[j], acc[i][j]);
    }

    #pragma unroll
    for (int i = 0; i < 8; i++) {
        int r = row0 + tr * 8 + i;
        if (r >= N_NODES) continue;
        #pragma unroll
        for (int j = 0; j < 6; j++) {
            int c = tc * 6 + j;
            if (c < 64)        g_Q[(size_t)r * 64 + c]        = acc[i][j];
            else if (c < 128)  g_K[(size_t)r * 64 + (c - 64)] = acc[i][j];
            else               g_V[(size_t)r * 64 + (c - 128)]= acc[i][j];
        }
    }
}

// ============================================================
// Kernel 2 (fused edge kernel): 64 edges per block.
//   Phase A: E = edge_attr @ We + be  (64x128 tile, thread 8x4)
//   Phase B: per (edge, head): score, e_t -> wE, a -> p = exp(a),
//            red-accumulate s, p*V[src], p*e_t into dst node slots.
// ============================================================
__global__ void edge_kernel(const float* __restrict__ ea,
                            const int*   __restrict__ ei,
                            const float* __restrict__ We,
                            const float* __restrict__ be,
                            const float* __restrict__ Aw,
                            float* __restrict__ wE) {
    extern __shared__ float sm[];
    float (*Wes)[128] = (float(*)[128])sm;              // 64 x 128  (32KB)
    float (*eaT)[65]  = (float(*)[65])(sm + 8192);      // 64 x 65   (aliased)
    float (*Es)[128]  = (float(*)[128])(sm + 8192);     // 64 x 128  (aliased, 32KB)

    const int tid = threadIdx.x;
    const int tr = tid >> 5;   // 0..7  -> rows tr*8..+7
    const int tc = tid & 31;   // 0..31 -> cols tc*4..+3
    const int e0 = blockIdx.x * 64;

    for (int i = tid; i < 64 * 128; i += 256)
        Wes[i >> 7][i & 127] = We[i];
    for (int i = tid; i < 64 * 64; i += 256) {
        int r = i >> 6, k = i & 63;
        eaT[k][r] = ea[(size_t)(e0 + r) * 64 + k];
    }
    __syncthreads();

    float acc[8][4];
    #pragma unroll
    for (int j = 0; j < 4; j++) {
        float b = be[tc * 4 + j];
        #pragma unroll
        for (int i = 0; i < 8; i++) acc[i][j] = b;
    }

    for (int k = 0; k < 64; k++) {
        float a[8], b[4];
        #pragma unroll
        for (int i = 0; i < 8; i++) a[i] = eaT[k][tr * 8 + i];
        #pragma unroll
        for (int j = 0; j < 4; j++) b[j] = Wes[k][tc * 4 + j];
        #pragma unroll
        for (int i = 0; i < 8; i++)
            #pragma unroll
            for (int j = 0; j < 4; j++)
                acc[i][j] = fmaf(a[i], b[j], acc[i][j]);
    }

    __syncthreads();   // all warps done reading eaT before Es overwrites it
    #pragma unroll
    for (int i = 0; i < 8; i++) {
        float4 v = make_float4(acc[i][0], acc[i][1], acc[i][2], acc[i][3]);
        *(float4*)&Es[tr * 8 + i][tc * 4] = v;
    }
    __syncthreads();

    // Phase B: 512 items = 64 edges x 8 heads, 2 per thread
    #pragma unroll
    for (int it = 0; it < 2; it++) {
        int item = tid + it * 256;
        int le = item >> 3;
        int h  = item & 7;
        int e  = e0 + le;
        int src = ei[e];
        int dst = ei[N_EDGES + e];

        const float4* Kp = (const float4*)&g_K[(size_t)src * 64 + h * 8];
        const float4* Qp = (const float4*)&g_Q[(size_t)dst * 64 + h * 8];
        const float4* Vp = (const float4*)&g_V[(size_t)src * 64 + h * 8];
        float4 k0 = Kp[0], k1 = Kp[1];
        float4 q0 = Qp[0], q1 = Qp[1];
        float4 v0 = Vp[0], v1 = Vp[1];

        float t[8];
        t[0] = k0.x + q0.x; t[1] = k0.y + q0.y; t[2] = k0.z + q0.z; t[3] = k0.w + q0.w;
        t[4] = k1.x + q1.x; t[5] = k1.y + q1.y; t[6] = k1.z + q1.z; t[7] = k1.w + q1.w;

        float et[8];
        #pragma unroll
        for (int d = 0; d < 8; d++) {
            float ew = Es[le][h * 16 + d];
            float eb = Es[le][h * 16 + 8 + d];
            float u = t[d] * ew;
            float sc = copysignf(sqrtf(fabsf(u)), u) + eb;
            et[d] = fmaxf(sc, 0.f);
        }

        float4* wp = (float4*)&wE[(size_t)e * 64 + h * 8];
        wp[0] = make_float4(et[0], et[1], et[2], et[3]);
        wp[1] = make_float4(et[4], et[5], et[6], et[7]);

        float a = 0.f;
        #pragma unroll
        for (int d = 0; d < 8; d++) a = fmaf(et[d], Aw[d * 8 + h], a);
        a = fminf(fmaxf(a, -CLAMP_V), CLAMP_V);
        float p = expf(a);

        atomicAdd(&g_s[(size_t)dst * 8 + h], p);
        float* wvp = &g_wV[(size_t)dst * 64 + h * 8];
        red_add_v4(wvp,     p * v0.x, p * v0.y, p * v0.z, p * v0.w);
        red_add_v4(wvp + 4, p * v1.x, p * v1.y, p * v1.z, p * v1.w);
        float* rwp = &g_row[(size_t)dst * 64 + h * 8];
        red_add_v4(rwp,     p * et[0], p * et[1], p * et[2], p * et[3]);
        red_add_v4(rwp + 4, p * et[4], p * et[5], p * et[6], p * et[7]);
    }
}

// ============================================================
// Kernel 3: finalize per (node, head):
//   out[n,h,c] = (wV_un[c] + sum_d row_un[d]*VeRow[d,h,c]) / (s + 1e-16)
// ============================================================
__global__ void finalize_kernel(const float* __restrict__ VeRow,
                                float* __restrict__ out) {
    __shared__ float Vr[512];   // [D][H][D]
    const int tid = threadIdx.x;
    for (int i = tid; i < 512; i += 256) Vr[i] = VeRow[i];
    __syncthreads();

    int idx = blockIdx.x * 256 + tid;
    if (idx >= N_NODES * HEADS) return;
    int n = idx >> 3, h = idx & 7;

    float s = g_s[idx];
    float inv = 1.f / (s + 1e-16f);

    const float4* wp = (const float4*)&g_wV[(size_t)n * 64 + h * 8];
    const float4* rp = (const float4*)&g_row[(size_t)n * 64 + h * 8];
    float4 w0 = wp[0], w1 = wp[1];
    float4 r0 = rp[0], r1 = rp[1];
    float wv[8] = {w0.x, w0.y, w0.z, w0.w, w1.x, w1.y, w1.z, w1.w};
    float rv[8] = {r0.x, r0.y, r0.z, r0.w, r1.x, r1.y, r1.z, r1.w};

    float o[8];
    #pragma unroll
    for (int c = 0; c < 8; c++) o[c] = wv[c];
    #pragma unroll
    for (int d = 0; d < 8; d++) {
        float r = rv[d];
        #pragma unroll
        for (int c = 0; c < 8; c++)
            o[c] = fmaf(r, Vr[d * 64 + h * 8 + c], o[c]);
    }
    #pragma unroll
    for (int c = 0; c < 8; c++) o[c] *= inv;

    float4* op = (float4*)&out[(size_t)n * 64 + h * 8];
    op[0] = make_float4(o[0], o[1], o[2], o[3]);
    op[1] = make_float4(o[4], o[5], o[6], o[7]);
}

// ============================================================
extern "C" void kernel_launch(void* const* d_in, const int* in_sizes, int n_in,
                              void* d_out, int out_size) {
    const float* x    = (const float*)d_in[0];
    const float* ea   = (const float*)d_in[1];
    const int*   ei   = (const int*)  d_in[2];
    const float* Wq   = (const float*)d_in[3];
    const float* bq   = (const float*)d_in[4];
    const float* Wk   = (const float*)d_in[5];
    const float* bk   = (const float*)d_in[6];
    const float* We   = (const float*)d_in[7];
    const float* be   = (const float*)d_in[8];
    const float* Wv   = (const float*)d_in[9];
    const float* bv   = (const float*)d_in[10];
    const float* Aw   = (const float*)d_in[11];
    const float* VeRow= (const float*)d_in[12];

    float* out = (float*)d_out;                       // h_out: [N, 64]
    float* wE  = out + (size_t)N_NODES * 64;          // wE:    [E, 64]

    void* p;
    cudaGetSymbolAddress(&p, g_s);   cudaMemsetAsync(p, 0, sizeof(float) * N_NODES * HEADS);
    cudaGetSymbolAddress(&p, g_wV);  cudaMemsetAsync(p, 0, sizeof(float) * N_NODES * HID);
    cudaGetSymbolAddress(&p, g_row); cudaMemsetAsync(p, 0, sizeof(float) * N_NODES * HID);

    const int qkv_smem  = (64 * 192 + 64 * 65) * (int)sizeof(float);   // ~65.8 KB
    const int edge_smem = (8192 + 8192) * (int)sizeof(float);          // 64 KB
    cudaFuncSetAttribute(qkv_kernel,  cudaFuncAttributeMaxDynamicSharedMemorySize, qkv_smem);
    cudaFuncSetAttribute(edge_kernel, cudaFuncAttributeMaxDynamicSharedMemorySize, edge_smem);

    qkv_kernel<<<(N_NODES + 63) / 64, 256, qkv_smem>>>(x, Wq, bq, Wk, bk, Wv, bv);
    edge_kernel<<<N_EDGES / 64, 256, edge_smem>>>(ea, ei, We, be, Aw, wE);
    finalize_kernel<<<(N_NODES * HEADS + 255) / 256, 256>>>(VeRow, out);
}

// round 2
// speedup vs baseline: 1.0677x; 1.0677x over previous
#include <cuda_runtime.h>
#include <math.h>

#define N_NODES 50000
#define N_EDGES 800000
#define HEADS 8
#define ODIM 8
#define HID 64          // HEADS*ODIM
#define CLAMP_V 5.0f

typedef unsigned long long u64;

// Scratch (static __device__ — no allocations allowed)
__device__ float g_Q[N_NODES * HID];
__device__ float g_K[N_NODES * HID];
__device__ float g_V[N_NODES * HID];
__device__ float g_s[N_NODES * HEADS];     // sum of exp(a) per (node, head)
__device__ float g_wV[N_NODES * HID];      // unnormalized sum p * V[src]
__device__ float g_row[N_NODES * HID];     // unnormalized sum p * e_t

__device__ __forceinline__ void red_add_v4(float* ptr, float a, float b, float c, float d) {
    asm volatile("red.global.add.v4.f32 [%0], {%1,%2,%3,%4};"
                 :: "l"(ptr), "f"(a), "f"(b), "f"(c), "f"(d) : "memory");
}

// Packed fp32x2 FMA (sm_103a FFMA2): 2 exact fp32 MACs per fma-pipe slot
__device__ __forceinline__ u64 pack_dup(float x) {
    u64 r;
    asm("mov.b64 %0, {%1, %1};" : "=l"(r) : "f"(x));
    return r;
}
__device__ __forceinline__ void ffma2(u64 &d, u64 a, u64 b) {
    asm("fma.rn.f32x2 %0, %1, %2, %0;" : "+l"(d) : "l"(a), "l"(b));
}
__device__ __forceinline__ float2 unpack2(u64 v) {
    float2 f;
    asm("mov.b64 {%0, %1}, %2;" : "=f"(f.x), "=f"(f.y) : "l"(v));
    return f;
}

// ============================================================
// Kernel 1: Q/K/V = x @ [Wq|Wk|Wv] + bias.  64 rows per block,
// 256 threads; per-thread tile 8 rows x 6 cols, rows packed f32x2.
// ============================================================
__global__ void qkv_kernel(const float* __restrict__ x,
                           const float* __restrict__ Wq, const float* __restrict__ bq,
                           const float* __restrict__ Wk, const float* __restrict__ bk,
                           const float* __restrict__ Wv, const float* __restrict__ bv) {
    extern __shared__ float sm[];
    float (*Ws)[192] = (float(*)[192])sm;                 // 64 x 192
    float (*xT)[72]  = (float(*)[72])(sm + 64 * 192);     // 64 x 72 (16B-aligned rows)

    const int tid = threadIdx.x;
    const int tr = tid >> 5;    // 0..7  -> rows tr*8 .. tr*8+7
    const int tc = tid & 31;    // 0..31 -> cols tc*6 .. tc*6+5
    const int row0 = blockIdx.x * 64;

    for (int i = tid; i < 64 * 64; i += 256) {
        int k = i >> 6, c = i & 63;
        Ws[k][c]       = Wq[i];
        Ws[k][c + 64]  = Wk[i];
        Ws[k][c + 128] = Wv[i];
    }
    for (int i = tid; i < 64 * 64; i += 256) {
        int r = i >> 6, k = i & 63;
        float v = (row0 + r < N_NODES) ? x[(size_t)(row0 + r) * 64 + k] : 0.f;
        xT[k][r] = v;
    }
    __syncthreads();

    // acc2[i][j]: rows (tr*8+2i, tr*8+2i+1), col tc*6+j
    u64 acc2[4][6];
    #pragma unroll
    for (int j = 0; j < 6; j++) {
        int c = tc * 6 + j;
        float b = (c < 64) ? bq[c] : (c < 128 ? bk[c - 64] : bv[c - 128]);
        u64 bb = pack_dup(b);
        #pragma unroll
        for (int i = 0; i < 4; i++) acc2[i][j] = bb;
    }

    for (int k = 0; k < 64; k++) {
        const u64* ap = (const u64*)&xT[k][tr * 8];   // 4 row-pairs (broadcast)
        u64 a0 = ap[0], a1 = ap[1], a2 = ap[2], a3 = ap[3];
        #pragma unroll
        for (int j = 0; j < 6; j++) {
            u64 b = pack_dup(Ws[k][tc * 6 + j]);
            ffma2(acc2[0][j], a0, b);
            ffma2(acc2[1][j], a1, b);
            ffma2(acc2[2][j], a2, b);
            ffma2(acc2[3][j], a3, b);
        }
    }

    #pragma unroll
    for (int i = 0; i < 4; i++) {
        #pragma unroll
        for (int j = 0; j < 6; j++) {
            float2 v = unpack2(acc2[i][j]);
            int c = tc * 6 + j;
            int r0 = row0 + tr * 8 + 2 * i;
            if (r0 < N_NODES) {
                float* dst = (c < 64) ? &g_Q[(size_t)r0 * 64 + c]
                           : (c < 128) ? &g_K[(size_t)r0 * 64 + (c - 64)]
                                       : &g_V[(size_t)r0 * 64 + (c - 128)];
                dst[0] = v.x;
                if (r0 + 1 < N_NODES) dst[64] = v.y;
            }
        }
    }
}

// ============================================================
// Kernel 2 (fused edge kernel): 64 edges per block.
//   Phase A: E = edge_attr @ We + be  (64x128 tile, rows packed f32x2)
//   Phase B: per (edge, head): score, e_t -> wE, a -> p = exp(a),
//            red-accumulate s, p*V[src], p*e_t into dst node slots.
// ============================================================
__global__ void edge_kernel(const float* __restrict__ ea,
                            const int*   __restrict__ ei,
                            const float* __restrict__ We,
                            const float* __restrict__ be,
                            const float* __restrict__ Aw,
                            float* __restrict__ wE) {
    extern __shared__ float sm[];
    float (*Wes)[128] = (float(*)[128])sm;              // 64 x 128  (32KB)
    float (*eaT)[72]  = (float(*)[72])(sm + 8192);      // 64 x 72   (aliased)
    float (*Es)[128]  = (float(*)[128])(sm + 8192);     // 64 x 128  (aliased, 32KB)

    const int tid = threadIdx.x;
    const int tr = tid >> 5;   // 0..7  -> rows tr*8..+7
    const int tc = tid & 31;   // 0..31 -> cols tc*4..+3
    const int e0 = blockIdx.x * 64;

    for (int i = tid; i < 64 * 128; i += 256)
        Wes[i >> 7][i & 127] = We[i];
    for (int i = tid; i < 64 * 64; i += 256) {
        int r = i >> 6, k = i & 63;
        eaT[k][r] = ea[(size_t)(e0 + r) * 64 + k];
    }
    __syncthreads();

    // acc2[i][j]: rows (tr*8+2i, tr*8+2i+1), col tc*4+j
    u64 acc2[4][4];
    #pragma unroll
    for (int j = 0; j < 4; j++) {
        u64 bb = pack_dup(be[tc * 4 + j]);
        #pragma unroll
        for (int i = 0; i < 4; i++) acc2[i][j] = bb;
    }

    for (int k = 0; k < 64; k++) {
        const u64* ap = (const u64*)&eaT[k][tr * 8];   // 4 row-pairs (broadcast)
        u64 a0 = ap[0], a1 = ap[1], a2 = ap[2], a3 = ap[3];
        float4 bf = *(const float4*)&Wes[k][tc * 4];
        u64 b0 = pack_dup(bf.x), b1 = pack_dup(bf.y), b2 = pack_dup(bf.z), b3 = pack_dup(bf.w);
        ffma2(acc2[0][0], a0, b0); ffma2(acc2[0][1], a0, b1); ffma2(acc2[0][2], a0, b2); ffma2(acc2[0][3], a0, b3);
        ffma2(acc2[1][0], a1, b0); ffma2(acc2[1][1], a1, b1); ffma2(acc2[1][2], a1, b2); ffma2(acc2[1][3], a1, b3);
        ffma2(acc2[2][0], a2, b0); ffma2(acc2[2][1], a2, b1); ffma2(acc2[2][2], a2, b2); ffma2(acc2[2][3], a2, b3);
        ffma2(acc2[3][0], a3, b0); ffma2(acc2[3][1], a3, b1); ffma2(acc2[3][2], a3, b2); ffma2(acc2[3][3], a3, b3);
    }

    __syncthreads();   // all warps done reading eaT before Es overwrites it
    #pragma unroll
    for (int i = 0; i < 4; i++) {
        float2 u0 = unpack2(acc2[i][0]), u1 = unpack2(acc2[i][1]);
        float2 u2 = unpack2(acc2[i][2]), u3 = unpack2(acc2[i][3]);
        *(float4*)&Es[tr * 8 + 2 * i][tc * 4]     = make_float4(u0.x, u1.x, u2.x, u3.x);
        *(float4*)&Es[tr * 8 + 2 * i + 1][tc * 4] = make_float4(u0.y, u1.y, u2.y, u3.y);
    }
    __syncthreads();

    // Phase B: 512 items = 64 edges x 8 heads, 2 per thread
    #pragma unroll
    for (int it = 0; it < 2; it++) {
        int item = tid + it * 256;
        int le = item >> 3;
        int h  = item & 7;
        int e  = e0 + le;
        int src = ei[e];
        int dst = ei[N_EDGES + e];

        const float4* Kp = (const float4*)&g_K[(size_t)src * 64 + h * 8];
        const float4* Qp = (const float4*)&g_Q[(size_t)dst * 64 + h * 8];
        const float4* Vp = (const float4*)&g_V[(size_t)src * 64 + h * 8];
        float4 k0 = Kp[0], k1 = Kp[1];
        float4 q0 = Qp[0], q1 = Qp[1];
        float4 v0 = Vp[0], v1 = Vp[1];

        float t[8];
        t[0] = k0.x + q0.x; t[1] = k0.y + q0.y; t[2] = k0.z + q0.z; t[3] = k0.w + q0.w;
        t[4] = k1.x + q1.x; t[5] = k1.y + q1.y; t[6] = k1.z + q1.z; t[7] = k1.w + q1.w;

        float et[8];
        #pragma unroll
        for (int d = 0; d < 8; d++) {
            float ew = Es[le][h * 16 + d];
            float eb = Es[le][h * 16 + 8 + d];
            float u = t[d] * ew;
            float sc = copysignf(sqrtf(fabsf(u)), u) + eb;
            et[d] = fmaxf(sc, 0.f);
        }

        float4* wp = (float4*)&wE[(size_t)e * 64 + h * 8];
        wp[0] = make_float4(et[0], et[1], et[2], et[3]);
        wp[1] = make_float4(et[4], et[5], et[6], et[7]);

        float a = 0.f;
        #pragma unroll
        for (int d = 0; d < 8; d++) a = fmaf(et[d], Aw[d * 8 + h], a);
        a = fminf(fmaxf(a, -CLAMP_V), CLAMP_V);
        float p = expf(a);

        atomicAdd(&g_s[(size_t)dst * 8 + h], p);
        float* wvp = &g_wV[(size_t)dst * 64 + h * 8];
        red_add_v4(wvp,     p * v0.x, p * v0.y, p * v0.z, p * v0.w);
        red_add_v4(wvp + 4, p * v1.x, p * v1.y, p * v1.z, p * v1.w);
        float* rwp = &g_row[(size_t)dst * 64 + h * 8];
        red_add_v4(rwp,     p * et[0], p * et[1], p * et[2], p * et[3]);
        red_add_v4(rwp + 4, p * et[4], p * et[5], p * et[6], p * et[7]);
    }
}

// ============================================================
// Kernel 3: finalize per (node, head):
//   out[n,h,c] = (wV_un[c] + sum_d row_un[d]*VeRow[d,h,c]) / (s + 1e-16)
// ============================================================
__global__ void finalize_kernel(const float* __restrict__ VeRow,
                                float* __restrict__ out) {
    __shared__ float Vr[512];   // [D][H][D]
    const int tid = threadIdx.x;
    for (int i = tid; i < 512; i += 256) Vr[i] = VeRow[i];
    __syncthreads();

    int idx = blockIdx.x * 256 + tid;
    if (idx >= N_NODES * HEADS) return;
    int n = idx >> 3, h = idx & 7;

    float s = g_s[idx];
    float inv = 1.f / (s + 1e-16f);

    const float4* wp = (const float4*)&g_wV[(size_t)n * 64 + h * 8];
    const float4* rp = (const float4*)&g_row[(size_t)n * 64 + h * 8];
    float4 w0 = wp[0], w1 = wp[1];
    float4 r0 = rp[0], r1 = rp[1];
    float wv[8] = {w0.x, w0.y, w0.z, w0.w, w1.x, w1.y, w1.z, w1.w};
    float rv[8] = {r0.x, r0.y, r0.z, r0.w, r1.x, r1.y, r1.z, r1.w};

    float o[8];
    #pragma unroll
    for (int c = 0; c < 8; c++) o[c] = wv[c];
    #pragma unroll
    for (int d = 0; d < 8; d++) {
        float r = rv[d];
        #pragma unroll
        for (int c = 0; c < 8; c++)
            o[c] = fmaf(r, Vr[d * 64 + h * 8 + c], o[c]);
    }
    #pragma unroll
    for (int c = 0; c < 8; c++) o[c] *= inv;

    float4* op = (float4*)&out[(size_t)n * 64 + h * 8];
    op[0] = make_float4(o[0], o[1], o[2], o[3]);
    op[1] = make_float4(o[4], o[5], o[6], o[7]);
}

// ============================================================
extern "C" void kernel_launch(void* const* d_in, const int* in_sizes, int n_in,
                              void* d_out, int out_size) {
    const float* x    = (const float*)d_in[0];
    const float* ea   = (const float*)d_in[1];
    const int*   ei   = (const int*)  d_in[2];
    const float* Wq   = (const float*)d_in[3];
    const float* bq   = (const float*)d_in[4];
    const float* Wk   = (const float*)d_in[5];
    const float* bk   = (const float*)d_in[6];
    const float* We   = (const float*)d_in[7];
    const float* be   = (const float*)d_in[8];
    const float* Wv   = (const float*)d_in[9];
    const float* bv   = (const float*)d_in[10];
    const float* Aw   = (const float*)d_in[11];
    const float* VeRow= (const float*)d_in[12];

    float* out = (float*)d_out;                       // h_out: [N, 64]
    float* wE  = out + (size_t)N_NODES * 64;          // wE:    [E, 64]

    void* p;
    cudaGetSymbolAddress(&p, g_s);   cudaMemsetAsync(p, 0, sizeof(float) * N_NODES * HEADS);
    cudaGetSymbolAddress(&p, g_wV);  cudaMemsetAsync(p, 0, sizeof(float) * N_NODES * HID);
    cudaGetSymbolAddress(&p, g_row); cudaMemsetAsync(p, 0, sizeof(float) * N_NODES * HID);

    const int qkv_smem  = (64 * 192 + 64 * 72) * (int)sizeof(float);   // ~67.6 KB
    const int edge_smem = (8192 + 8192) * (int)sizeof(float);          // 64 KB
    cudaFuncSetAttribute(qkv_kernel,  cudaFuncAttributeMaxDynamicSharedMemorySize, qkv_smem);
    cudaFuncSetAttribute(edge_kernel, cudaFuncAttributeMaxDynamicSharedMemorySize, edge_smem);

    qkv_kernel<<<(N_NODES + 63) / 64, 256, qkv_smem>>>(x, Wq, bq, Wk, bk, Wv, bv);
    edge_kernel<<<N_EDGES / 64, 256, edge_smem>>>(ea, ei, We, be, Aw, wE);
    finalize_kernel<<<(N_NODES * HEADS + 255) / 256, 256>>>(VeRow, out);
}

// round 4
// speedup vs baseline: 1.8460x; 1.7290x over previous
#include <cuda_runtime.h>
#include <cuda_bf16.h>
#include <math.h>
#include <cstdint>

#define N_NODES 50000
#define N_EDGES 800000
#define HEADS 8
#define HID 64
#define CLAMP_V 5.0f

// ---------------- device scratch (zero-init at module load) ----------------
__device__ float g_Q[N_NODES * HID];
__device__ float g_K[N_NODES * HID];
__device__ float g_V[N_NODES * HID];
__device__ float g_s[N_NODES * HEADS];
__device__ float g_wV[N_NODES * HID];
__device__ float g_row[N_NODES * HID];
// We^T split to bf16 hi/lo: [n=128][k=64], row-major
__device__ unsigned short g_BhiT[128 * 64];
__device__ unsigned short g_BloT[128 * 64];

// ---------------- helpers ----------------
__device__ __forceinline__ void red_add_v4(float* ptr, float a, float b, float c, float d) {
    asm volatile("red.global.add.v4.f32 [%0], {%1,%2,%3,%4};"
                 :: "l"(ptr), "f"(a), "f"(b), "f"(c), "f"(d) : "memory");
}
__device__ __forceinline__ float sqrt_approx(float x) {
    float r; asm("sqrt.approx.f32 %0, %1;" : "=f"(r) : "f"(x)); return r;
}
// hi/lo bf16 split of a float pair; packed regs in mem order [x, y]
__device__ __forceinline__ void split2(float x, float y, uint32_t& hi, uint32_t& lo) {
    uint32_t xb = __float_as_uint(x), yb = __float_as_uint(y);
    float xh = __uint_as_float((xb + 0x8000u) & 0xFFFF0000u);
    float yh = __uint_as_float((yb + 0x8000u) & 0xFFFF0000u);
    float xl = x - xh, yl = y - yh;
    asm("cvt.rn.bf16x2.f32 %0, %1, %2;" : "=r"(hi) : "f"(yh), "f"(xh));
    asm("cvt.rn.bf16x2.f32 %0, %1, %2;" : "=r"(lo) : "f"(yl), "f"(xl));
}
__device__ __forceinline__ void mma_bf16(float* c, const uint32_t* a, uint32_t b0, uint32_t b1) {
    asm volatile(
        "mma.sync.aligned.m16n8k16.row.col.f32.bf16.bf16.f32 "
        "{%0,%1,%2,%3}, {%4,%5,%6,%7}, {%8,%9}, {%0,%1,%2,%3};"
        : "+f"(c[0]), "+f"(c[1]), "+f"(c[2]), "+f"(c[3])
        : "r"(a[0]), "r"(a[1]), "r"(a[2]), "r"(a[3]), "r"(b0), "r"(b1));
}

// ============================================================
// Kernel 1: QKV (scalar GEMM) + last block preps We^T hi/lo
// ============================================================
__global__ void qkv_kernel(const float* __restrict__ x,
                           const float* __restrict__ Wq, const float* __restrict__ bq,
                           const float* __restrict__ Wk, const float* __restrict__ bk,
                           const float* __restrict__ Wv, const float* __restrict__ bv,
                           const float* __restrict__ We) {
    const int tid = threadIdx.x;

    if (blockIdx.x == gridDim.x - 1) {
        // prep: We [64k][128n] -> B^T [n][k] bf16 hi/lo
        for (int idx = tid; idx < 128 * 64; idx += 256) {
            int n = idx >> 6, k = idx & 63;
            float v = We[k * 128 + n];
            uint32_t vb = __float_as_uint(v);
            float vh = __uint_as_float((vb + 0x8000u) & 0xFFFF0000u);
            float vl = v - vh;
            unsigned short hs = (unsigned short)((vb + 0x8000u) >> 16);
            unsigned short ls; asm("cvt.rn.bf16.f32 %0, %1;" : "=h"(ls) : "f"(vl));
            g_BhiT[n * 64 + k] = hs;
            g_BloT[n * 64 + k] = ls;
        }
        return;
    }

    extern __shared__ float sm[];
    float (*Ws)[192] = (float(*)[192])sm;
    float (*xT)[72]  = (float(*)[72])(sm + 64 * 192);

    const int tr = tid >> 5;
    const int tc = tid & 31;
    const int row0 = blockIdx.x * 64;

    for (int i = tid; i < 64 * 64; i += 256) {
        int k = i >> 6, c = i & 63;
        Ws[k][c]       = Wq[i];
        Ws[k][c + 64]  = Wk[i];
        Ws[k][c + 128] = Wv[i];
    }
    for (int i = tid; i < 64 * 64; i += 256) {
        int r = i >> 6, k = i & 63;
        float v = (row0 + r < N_NODES) ? x[(size_t)(row0 + r) * 64 + k] : 0.f;
        xT[k][r] = v;
    }
    __syncthreads();

    float acc[8][6];
    #pragma unroll
    for (int j = 0; j < 6; j++) {
        int c = tc * 6 + j;
        float b = (c < 64) ? bq[c] : (c < 128 ? bk[c - 64] : bv[c - 128]);
        #pragma unroll
        for (int i = 0; i < 8; i++) acc[i][j] = b;
    }
    for (int k = 0; k < 64; k++) {
        float a[8], b[6];
        #pragma unroll
        for (int i = 0; i < 8; i++) a[i] = xT[k][tr * 8 + i];
        #pragma unroll
        for (int j = 0; j < 6; j++) b[j] = Ws[k][tc * 6 + j];
        #pragma unroll
        for (int i = 0; i < 8; i++)
            #pragma unroll
            for (int j = 0; j < 6; j++)
                acc[i][j] = fmaf(a[i], b[j], acc[i][j]);
    }
    #pragma unroll
    for (int i = 0; i < 8; i++) {
        int r = row0 + tr * 8 + i;
        if (r >= N_NODES) continue;
        #pragma unroll
        for (int j = 0; j < 6; j++) {
            int c = tc * 6 + j;
            if (c < 64)        g_Q[(size_t)r * 64 + c]         = acc[i][j];
            else if (c < 128)  g_K[(size_t)r * 64 + (c - 64)]  = acc[i][j];
            else               g_V[(size_t)r * 64 + (c - 128)] = acc[i][j];
        }
    }
}

// ============================================================
// Kernel 2: fused edge kernel, 64 edges/block, mma.sync bf16 GEMM
// ============================================================
// smem byte offsets
#define SM_BE    0                       // be[128] floats
#define SM_AW    512                     // Aw[64] floats
#define SM_AHI   1024                    // [64][72] bf16 = 9216
#define SM_ALO   (SM_AHI + 9216)
#define SM_BHI   (SM_ALO + 9216)         // [128][72] bf16 = 18432
#define SM_BLO   (SM_BHI + 18432)
#define SM_TOTAL (SM_BLO + 18432)        // 56320
#define SM_ES    1024                    // alias: [64 edges][8 h][20] floats = 40960

__global__ __launch_bounds__(256, 3)
void edge_kernel(const float* __restrict__ ea,
                 const int*   __restrict__ ei,
                 const float* __restrict__ be,
                 const float* __restrict__ Aw,
                 float* __restrict__ wE) {
    extern __shared__ char smc[];
    float* sbe = (float*)(smc + SM_BE);
    float* sAw = (float*)(smc + SM_AW);
    const int tid = threadIdx.x;
    const int e0 = blockIdx.x * 64;

    if (tid < 128) sbe[tid] = be[tid];
    else if (tid < 192) sAw[tid - 128] = Aw[tid - 128];

    // A tiles: ea[e0..e0+63][0..63] -> bf16 hi/lo, rows padded to 72
    #pragma unroll
    for (int it = 0; it < 4; it++) {
        int idx = tid + it * 256;          // 0..1023 float4s
        int r = idx >> 4, k0 = (idx & 15) * 4;
        float4 v = *(const float4*)&ea[(size_t)(e0 + r) * 64 + k0];
        uint32_t h01, l01, h23, l23;
        split2(v.x, v.y, h01, l01);
        split2(v.z, v.w, h23, l23);
        uint32_t off = (uint32_t)r * 144 + k0 * 2;   // bytes within tile
        *(uint2*)(smc + SM_AHI + off) = make_uint2(h01, h23);
        *(uint2*)(smc + SM_ALO + off) = make_uint2(l01, l23);
    }
    // B tiles: copy [128][64] -> [128][72]
    #pragma unroll
    for (int it = 0; it < 8; it++) {
        int idx = tid + it * 256;          // 0..2047 uint2 (4 bf16)
        int r = idx >> 4, c = (idx & 15) * 4;
        uint32_t off = (uint32_t)r * 144 + c * 2;
        *(uint2*)(smc + SM_BHI + off) = *(const uint2*)&g_BhiT[r * 64 + c];
        *(uint2*)(smc + SM_BLO + off) = *(const uint2*)&g_BloT[r * 64 + c];
    }
    __syncthreads();

    // -------- GEMM: D[64 x 128] = A(64x64) @ B^T(128x64)^T, 3-term split --------
    const int lane = tid & 31;
    const int w = tid >> 5;
    const int wm = w >> 2;                 // 0..1 : rows wm*32
    const int wn = w & 3;                  // 0..3 : cols wn*32
    const int g = lane >> 2, t2 = (lane & 3) * 2;

    const unsigned short* Ah = (const unsigned short*)(smc + SM_AHI);
    const unsigned short* Al = (const unsigned short*)(smc + SM_ALO);
    const unsigned short* Bh = (const unsigned short*)(smc + SM_BHI);
    const unsigned short* Bl = (const unsigned short*)(smc + SM_BLO);

    float acc[2][4][4];
    #pragma unroll
    for (int mt = 0; mt < 2; mt++)
        #pragma unroll
        for (int nt = 0; nt < 4; nt++)
            #pragma unroll
            for (int i = 0; i < 4; i++) acc[mt][nt][i] = 0.f;

    #pragma unroll
    for (int kk = 0; kk < 4; kk++) {
        const int k0 = kk * 16;
        uint32_t ah[2][4], al[2][4];
        #pragma unroll
        for (int mt = 0; mt < 2; mt++) {
            int r = wm * 32 + mt * 16 + g;
            ah[mt][0] = *(const uint32_t*)&Ah[(r    ) * 72 + k0 + t2];
            ah[mt][1] = *(const uint32_t*)&Ah[(r + 8) * 72 + k0 + t2];
            ah[mt][2] = *(const uint32_t*)&Ah[(r    ) * 72 + k0 + t2 + 8];
            ah[mt][3] = *(const uint32_t*)&Ah[(r + 8) * 72 + k0 + t2 + 8];
            al[mt][0] = *(const uint32_t*)&Al[(r    ) * 72 + k0 + t2];
            al[mt][1] = *(const uint32_t*)&Al[(r + 8) * 72 + k0 + t2];
            al[mt][2] = *(const uint32_t*)&Al[(r    ) * 72 + k0 + t2 + 8];
            al[mt][3] = *(const uint32_t*)&Al[(r + 8) * 72 + k0 + t2 + 8];
        }
        #pragma unroll
        for (int nt = 0; nt < 4; nt++) {
            int n = wn * 32 + nt * 8 + g;
            uint32_t bh0 = *(const uint32_t*)&Bh[n * 72 + k0 + t2];
            uint32_t bh1 = *(const uint32_t*)&Bh[n * 72 + k0 + t2 + 8];
            uint32_t bl0 = *(const uint32_t*)&Bl[n * 72 + k0 + t2];
            uint32_t bl1 = *(const uint32_t*)&Bl[n * 72 + k0 + t2 + 8];
            #pragma unroll
            for (int mt = 0; mt < 2; mt++) {
                mma_bf16(acc[mt][nt], ah[mt], bh0, bh1);
                mma_bf16(acc[mt][nt], ah[mt], bl0, bl1);
                mma_bf16(acc[mt][nt], al[mt], bh0, bh1);
            }
        }
    }
    __syncthreads();   // all A/B reads done before Es aliases the region

    // stage D + bias into Es: layout [edge][h][20] floats
    float* Es = (float*)(smc + SM_ES);
    #pragma unroll
    for (int mt = 0; mt < 2; mt++) {
        #pragma unroll
        for (int nt = 0; nt < 4; nt++) {
            int row = wm * 32 + mt * 16 + g;
            int col = wn * 32 + nt * 8 + t2;
            int h = col >> 4, d = col & 15;
            float b0 = sbe[col], b1 = sbe[col + 1];
            int i0 = row * 160 + h * 20 + d;
            Es[i0]     = acc[mt][nt][0] + b0;
            Es[i0 + 1] = acc[mt][nt][1] + b1;
            int i1 = (row + 8) * 160 + h * 20 + d;
            Es[i1]     = acc[mt][nt][2] + b0;
            Es[i1 + 1] = acc[mt][nt][3] + b1;
        }
    }
    __syncthreads();

    // -------- Phase B: 512 items = 64 edges x 8 heads, 2 per thread --------
    #pragma unroll
    for (int it = 0; it < 2; it++) {
        int item = tid + it * 256;
        int le = item >> 3;
        int h  = item & 7;
        int e  = e0 + le;
        int src = ei[e];
        int dst = ei[N_EDGES + e];

        const float4* Kp = (const float4*)&g_K[(size_t)src * 64 + h * 8];
        const float4* Qp = (const float4*)&g_Q[(size_t)dst * 64 + h * 8];
        const float4* Vp = (const float4*)&g_V[(size_t)src * 64 + h * 8];
        float4 k0 = Kp[0], k1 = Kp[1];
        float4 q0 = Qp[0], q1 = Qp[1];
        float4 v0 = Vp[0], v1 = Vp[1];

        float t[8];
        t[0] = k0.x + q0.x; t[1] = k0.y + q0.y; t[2] = k0.z + q0.z; t[3] = k0.w + q0.w;
        t[4] = k1.x + q1.x; t[5] = k1.y + q1.y; t[6] = k1.z + q1.z; t[7] = k1.w + q1.w;

        const float* ep = &Es[le * 160 + h * 20];
        float4 ew0 = *(const float4*)&ep[0];
        float4 ew1 = *(const float4*)&ep[4];
        float4 eb0 = *(const float4*)&ep[8];
        float4 eb1 = *(const float4*)&ep[12];
        float ew[8] = {ew0.x, ew0.y, ew0.z, ew0.w, ew1.x, ew1.y, ew1.z, ew1.w};
        float eb[8] = {eb0.x, eb0.y, eb0.z, eb0.w, eb1.x, eb1.y, eb1.z, eb1.w};

        float et[8];
        #pragma unroll
        for (int d = 0; d < 8; d++) {
            float u = t[d] * ew[d];
            float sc = copysignf(sqrt_approx(fabsf(u)), u) + eb[d];
            et[d] = fmaxf(sc, 0.f);
        }

        float4* wp = (float4*)&wE[(size_t)e * 64 + h * 8];
        wp[0] = make_float4(et[0], et[1], et[2], et[3]);
        wp[1] = make_float4(et[4], et[5], et[6], et[7]);

        float a = 0.f;
        #pragma unroll
        for (int d = 0; d < 8; d++) a = fmaf(et[d], sAw[d * 8 + h], a);
        a = fminf(fmaxf(a, -CLAMP_V), CLAMP_V);
        float p = __expf(a);

        atomicAdd(&g_s[(size_t)dst * 8 + h], p);
        float* wvp = &g_wV[(size_t)dst * 64 + h * 8];
        red_add_v4(wvp,     p * v0.x, p * v0.y, p * v0.z, p * v0.w);
        red_add_v4(wvp + 4, p * v1.x, p * v1.y, p * v1.z, p * v1.w);
        float* rwp = &g_row[(size_t)dst * 64 + h * 8];
        red_add_v4(rwp,     p * et[0], p * et[1], p * et[2], p * et[3]);
        red_add_v4(rwp + 4, p * et[4], p * et[5], p * et[6], p * et[7]);
    }
}

// ============================================================
// Kernel 3: finalize + self-zero scratch for next replay
// ============================================================
__global__ void finalize_kernel(const float* __restrict__ VeRow,
                                float* __restrict__ out) {
    __shared__ float Vr[512];
    const int tid = threadIdx.x;
    for (int i = tid; i < 512; i += 256) Vr[i] = VeRow[i];
    __syncthreads();

    int idx = blockIdx.x * 256 + tid;
    if (idx >= N_NODES * HEADS) return;
    int n = idx >> 3, h = idx & 7;

    float s = g_s[idx];
    g_s[idx] = 0.f;
    float inv = 1.f / (s + 1e-16f);

    float4* wp = (float4*)&g_wV[(size_t)n * 64 + h * 8];
    float4* rp = (float4*)&g_row[(size_t)n * 64 + h * 8];
    float4 w0 = wp[0], w1 = wp[1];
    float4 r0 = rp[0], r1 = rp[1];
    float4 z = make_float4(0.f, 0.f, 0.f, 0.f);
    wp[0] = z; wp[1] = z; rp[0] = z; rp[1] = z;

    float wv[8] = {w0.x, w0.y, w0.z, w0.w, w1.x, w1.y, w1.z, w1.w};
    float rv[8] = {r0.x, r0.y, r0.z, r0.w, r1.x, r1.y, r1.z, r1.w};

    float o[8];
    #pragma unroll
    for (int c = 0; c < 8; c++) o[c] = wv[c];
    #pragma unroll
    for (int d = 0; d < 8; d++) {
        float r = rv[d];
        #pragma unroll
        for (int c = 0; c < 8; c++)
            o[c] = fmaf(r, Vr[d * 64 + h * 8 + c], o[c]);
    }
    #pragma unroll
    for (int c = 0; c < 8; c++) o[c] *= inv;

    float4* op = (float4*)&out[(size_t)n * 64 + h * 8];
    op[0] = make_float4(o[0], o[1], o[2], o[3]);
    op[1] = make_float4(o[4], o[5], o[6], o[7]);
}

// ============================================================
extern "C" void kernel_launch(void* const* d_in, const int* in_sizes, int n_in,
                              void* d_out, int out_size) {
    const float* x    = (const float*)d_in[0];
    const float* ea   = (const float*)d_in[1];
    const int*   ei   = (const int*)  d_in[2];
    const float* Wq   = (const float*)d_in[3];
    const float* bq   = (const float*)d_in[4];
    const float* Wk   = (const float*)d_in[5];
    const float* bk   = (const float*)d_in[6];
    const float* We   = (const float*)d_in[7];
    const float* be   = (const float*)d_in[8];
    const float* Wv   = (const float*)d_in[9];
    const float* bv   = (const float*)d_in[10];
    const float* Aw   = (const float*)d_in[11];
    const float* VeRow= (const float*)d_in[12];

    float* out = (float*)d_out;                  // h_out: [N, 64]
    float* wE  = out + (size_t)N_NODES * 64;     // wE:    [E, 64]

    const int qkv_smem = (64 * 192 + 64 * 72) * (int)sizeof(float);
    cudaFuncSetAttribute(qkv_kernel,  cudaFuncAttributeMaxDynamicSharedMemorySize, qkv_smem);
    cudaFuncSetAttribute(edge_kernel, cudaFuncAttributeMaxDynamicSharedMemorySize, SM_TOTAL);

    qkv_kernel<<<783, 256, qkv_smem>>>(x, Wq, bq, Wk, bk, Wv, bv, We);
    edge_kernel<<<N_EDGES / 64, 256, SM_TOTAL>>>(ea, ei, be, Aw, wE);
    finalize_kernel<<<(N_NODES * HEADS + 255) / 256, 256>>>(VeRow, out);
}

// round 5
// speedup vs baseline: 2.1534x; 1.1665x over previous
#include <cuda_runtime.h>
#include <cuda_bf16.h>
#include <math.h>
#include <cstdint>

#define N_NODES 50000
#define N_EDGES 800000
#define HEADS 8
#define HID 64
#define CLAMP_V 5.0f

// ---------------- device scratch (zero-init at module load) ----------------
__device__ float g_Q[N_NODES * HID];
__device__ float g_K[N_NODES * HID];
__device__ float g_V[N_NODES * HID];
__device__ float g_s[N_NODES * HEADS];
__device__ float g_wV[N_NODES * HID];
__device__ float g_row[N_NODES * HID];
// Pre-split weights, bf16 hi/lo, row-major [n][k]
__device__ unsigned short g_WhiT[192 * 64];   // [Wq|Wk|Wv]^T
__device__ unsigned short g_WloT[192 * 64];
__device__ unsigned short g_BhiT[128 * 64];   // We^T
__device__ unsigned short g_BloT[128 * 64];

// ---------------- helpers ----------------
__device__ __forceinline__ void red_add_v4(float* ptr, float a, float b, float c, float d) {
    asm volatile("red.global.add.v4.f32 [%0], {%1,%2,%3,%4};"
                 :: "l"(ptr), "f"(a), "f"(b), "f"(c), "f"(d) : "memory");
}
__device__ __forceinline__ float sqrt_approx(float x) {
    float r; asm("sqrt.approx.f32 %0, %1;" : "=f"(r) : "f"(x)); return r;
}
// hi/lo bf16 split of a float pair; packed regs in mem order [x, y]
__device__ __forceinline__ void split2(float x, float y, uint32_t& hi, uint32_t& lo) {
    uint32_t xb = __float_as_uint(x), yb = __float_as_uint(y);
    float xh = __uint_as_float((xb + 0x8000u) & 0xFFFF0000u);
    float yh = __uint_as_float((yb + 0x8000u) & 0xFFFF0000u);
    float xl = x - xh, yl = y - yh;
    asm("cvt.rn.bf16x2.f32 %0, %1, %2;" : "=r"(hi) : "f"(yh), "f"(xh));
    asm("cvt.rn.bf16x2.f32 %0, %1, %2;" : "=r"(lo) : "f"(yl), "f"(xl));
}
__device__ __forceinline__ void split1(float v, unsigned short& hs, unsigned short& ls) {
    uint32_t vb = __float_as_uint(v);
    float vh = __uint_as_float((vb + 0x8000u) & 0xFFFF0000u);
    float vl = v - vh;
    hs = (unsigned short)((vb + 0x8000u) >> 16);
    asm("cvt.rn.bf16.f32 %0, %1;" : "=h"(ls) : "f"(vl));
}
__device__ __forceinline__ void mma_bf16(float* c, const uint32_t* a, uint32_t b0, uint32_t b1) {
    asm volatile(
        "mma.sync.aligned.m16n8k16.row.col.f32.bf16.bf16.f32 "
        "{%0,%1,%2,%3}, {%4,%5,%6,%7}, {%8,%9}, {%0,%1,%2,%3};"
        : "+f"(c[0]), "+f"(c[1]), "+f"(c[2]), "+f"(c[3])
        : "r"(a[0]), "r"(a[1]), "r"(a[2]), "r"(a[3]), "r"(b0), "r"(b1));
}

// ============================================================
// Kernel 0: prep — split weights into bf16 hi/lo global images
// ============================================================
__global__ void prep_kernel(const float* __restrict__ Wq, const float* __restrict__ Wk,
                            const float* __restrict__ Wv, const float* __restrict__ We) {
    int idx = blockIdx.x * 256 + threadIdx.x;
    if (idx < 192 * 64) {
        int n = idx >> 6, k = idx & 63;
        float v = (n < 64) ? Wq[k * 64 + n]
                : (n < 128) ? Wk[k * 64 + (n - 64)]
                            : Wv[k * 64 + (n - 128)];
        unsigned short hs, ls;
        split1(v, hs, ls);
        g_WhiT[idx] = hs;
        g_WloT[idx] = ls;
    } else if (idx < 192 * 64 + 128 * 64) {
        int j = idx - 192 * 64;
        int n = j >> 6, k = j & 63;
        unsigned short hs, ls;
        split1(We[k * 128 + n], hs, ls);
        g_BhiT[j] = hs;
        g_BloT[j] = ls;
    }
}

// ============================================================
// Kernel 1: QKV via mma.sync bf16 hi/lo.  128 rows/block, 256 thr.
// ============================================================
#define QB_BIAS 0                         // 192 floats
#define QB_AHI  1024                      // [128][72] bf16 = 18432
#define QB_ALO  (QB_AHI + 18432)
#define QB_BHI  (QB_ALO + 18432)          // [192][72] bf16 = 27648
#define QB_BLO  (QB_BHI + 27648)
#define QB_TOTAL (QB_BLO + 27648)         // 93184

__global__ __launch_bounds__(256, 2)
void qkv_mma_kernel(const float* __restrict__ x,
                    const float* __restrict__ bq, const float* __restrict__ bk,
                    const float* __restrict__ bv) {
    extern __shared__ char smc[];
    float* sbias = (float*)(smc + QB_BIAS);
    const int tid = threadIdx.x;
    const int row0 = blockIdx.x * 128;

    if (tid < 192)
        sbias[tid] = (tid < 64) ? bq[tid] : (tid < 128) ? bk[tid - 64] : bv[tid - 128];

    // A: x[row0..row0+127][0..63] -> bf16 hi/lo, rows padded to 72
    #pragma unroll
    for (int it = 0; it < 8; it++) {
        int idx = tid + it * 256;              // 0..2047 float4s
        int r = idx >> 4, k0 = (idx & 15) * 4;
        float4 v = make_float4(0.f, 0.f, 0.f, 0.f);
        if (row0 + r < N_NODES) v = *(const float4*)&x[(size_t)(row0 + r) * 64 + k0];
        uint32_t h01, l01, h23, l23;
        split2(v.x, v.y, h01, l01);
        split2(v.z, v.w, h23, l23);
        uint32_t off = (uint32_t)r * 144 + k0 * 2;
        *(uint2*)(smc + QB_AHI + off) = make_uint2(h01, h23);
        *(uint2*)(smc + QB_ALO + off) = make_uint2(l01, l23);
    }
    // B: copy [192][64] -> [192][72]
    #pragma unroll
    for (int it = 0; it < 12; it++) {
        int idx = tid + it * 256;              // 0..3071 uint2 (4 bf16)
        int r = idx >> 4, c = (idx & 15) * 4;
        uint32_t off = (uint32_t)r * 144 + c * 2;
        *(uint2*)(smc + QB_BHI + off) = *(const uint2*)&g_WhiT[r * 64 + c];
        *(uint2*)(smc + QB_BLO + off) = *(const uint2*)&g_WloT[r * 64 + c];
    }
    __syncthreads();

    const int lane = tid & 31;
    const int w = tid >> 5;
    const int wm = w >> 1;                     // 0..3 : rows wm*32
    const int wn = w & 1;                      // 0..1 : cols wn*96 (12 n-tiles)
    const int g = lane >> 2, t2 = (lane & 3) * 2;

    const unsigned short* Ah = (const unsigned short*)(smc + QB_AHI);
    const unsigned short* Al = (const unsigned short*)(smc + QB_ALO);
    const unsigned short* Bh = (const unsigned short*)(smc + QB_BHI);
    const unsigned short* Bl = (const unsigned short*)(smc + QB_BLO);

    float acc[2][12][4];
    #pragma unroll
    for (int mt = 0; mt < 2; mt++)
        #pragma unroll
        for (int nt = 0; nt < 12; nt++)
            #pragma unroll
            for (int i = 0; i < 4; i++) acc[mt][nt][i] = 0.f;

    #pragma unroll
    for (int kk = 0; kk < 4; kk++) {
        const int k0 = kk * 16;
        uint32_t ah[2][4], al[2][4];
        #pragma unroll
        for (int mt = 0; mt < 2; mt++) {
            int r = wm * 32 + mt * 16 + g;
            ah[mt][0] = *(const uint32_t*)&Ah[(r    ) * 72 + k0 + t2];
            ah[mt][1] = *(const uint32_t*)&Ah[(r + 8) * 72 + k0 + t2];
            ah[mt][2] = *(const uint32_t*)&Ah[(r    ) * 72 + k0 + t2 + 8];
            ah[mt][3] = *(const uint32_t*)&Ah[(r + 8) * 72 + k0 + t2 + 8];
            al[mt][0] = *(const uint32_t*)&Al[(r    ) * 72 + k0 + t2];
            al[mt][1] = *(const uint32_t*)&Al[(r + 8) * 72 + k0 + t2];
            al[mt][2] = *(const uint32_t*)&Al[(r    ) * 72 + k0 + t2 + 8];
            al[mt][3] = *(const uint32_t*)&Al[(r + 8) * 72 + k0 + t2 + 8];
        }
        #pragma unroll
        for (int nt = 0; nt < 12; nt++) {
            int n = wn * 96 + nt * 8 + g;
            uint32_t bh0 = *(const uint32_t*)&Bh[n * 72 + k0 + t2];
            uint32_t bh1 = *(const uint32_t*)&Bh[n * 72 + k0 + t2 + 8];
            uint32_t bl0 = *(const uint32_t*)&Bl[n * 72 + k0 + t2];
            uint32_t bl1 = *(const uint32_t*)&Bl[n * 72 + k0 + t2 + 8];
            #pragma unroll
            for (int mt = 0; mt < 2; mt++) {
                mma_bf16(acc[mt][nt], ah[mt], bh0, bh1);
                mma_bf16(acc[mt][nt], ah[mt], bl0, bl1);
                mma_bf16(acc[mt][nt], al[mt], bh0, bh1);
            }
        }
    }

    // store fragments directly (quad-coalesced 8B stores)
    #pragma unroll
    for (int nt = 0; nt < 12; nt++) {
        int col = wn * 96 + nt * 8 + t2;
        float b0 = sbias[col], b1 = sbias[col + 1];
        float* base = (col < 64) ? &g_Q[col]
                    : (col < 128) ? &g_K[col - 64]
                                  : &g_V[col - 128];
        #pragma unroll
        for (int mt = 0; mt < 2; mt++) {
            int r = row0 + wm * 32 + mt * 16 + g;
            if (r < N_NODES)
                *(float2*)&base[(size_t)r * 64] = make_float2(acc[mt][nt][0] + b0, acc[mt][nt][1] + b1);
            if (r + 8 < N_NODES)
                *(float2*)&base[(size_t)(r + 8) * 64] = make_float2(acc[mt][nt][2] + b0, acc[mt][nt][3] + b1);
        }
    }
}

// ============================================================
// Kernel 2: fused edge kernel, 128 edges/block, 512 threads
// ============================================================
#define SM_BE    0                       // be[128] floats
#define SM_AW    512                     // Aw[64] floats
#define SM_AHI   1024                    // [128][72] bf16 = 18432
#define SM_ALO   (SM_AHI + 18432)
#define SM_BHI   (SM_ALO + 18432)        // [128][72] bf16 = 18432
#define SM_BLO   (SM_BHI + 18432)
#define SM_ES    1024                    // alias: [128 edges][164] floats
#define ES_STRIDE 164
#define SM_TOTAL (1024 + 128 * ES_STRIDE * 4)   // 84992

__global__ __launch_bounds__(512, 2)
void edge_kernel(const float* __restrict__ ea,
                 const int*   __restrict__ ei,
                 const float* __restrict__ be,
                 const float* __restrict__ Aw,
                 float* __restrict__ wE) {
    extern __shared__ char smc[];
    float* sbe = (float*)(smc + SM_BE);
    float* sAw = (float*)(smc + SM_AW);
    const int tid = threadIdx.x;
    const int e0 = blockIdx.x * 128;

    if (tid < 128) sbe[tid] = be[tid];
    else if (tid < 192) sAw[tid - 128] = Aw[tid - 128];

    // A: ea[e0..e0+127][0..63] -> bf16 hi/lo, rows padded to 72
    #pragma unroll
    for (int it = 0; it < 4; it++) {
        int idx = tid + it * 512;          // 0..2047 float4s
        int r = idx >> 4, k0 = (idx & 15) * 4;
        float4 v = *(const float4*)&ea[(size_t)(e0 + r) * 64 + k0];
        uint32_t h01, l01, h23, l23;
        split2(v.x, v.y, h01, l01);
        split2(v.z, v.w, h23, l23);
        uint32_t off = (uint32_t)r * 144 + k0 * 2;
        *(uint2*)(smc + SM_AHI + off) = make_uint2(h01, h23);
        *(uint2*)(smc + SM_ALO + off) = make_uint2(l01, l23);
    }
    // B: copy [128][64] -> [128][72]
    #pragma unroll
    for (int it = 0; it < 4; it++) {
        int idx = tid + it * 512;          // 0..2047 uint2 (4 bf16)
        int r = idx >> 4, c = (idx & 15) * 4;
        uint32_t off = (uint32_t)r * 144 + c * 2;
        *(uint2*)(smc + SM_BHI + off) = *(const uint2*)&g_BhiT[r * 64 + c];
        *(uint2*)(smc + SM_BLO + off) = *(const uint2*)&g_BloT[r * 64 + c];
    }
    __syncthreads();

    // -------- GEMM: D[128 x 128] = A(128x64) @ B^T(128x64)^T, 3-term --------
    const int lane = tid & 31;
    const int w = tid >> 5;                // 0..15
    const int wm = w >> 2;                 // 0..3 : rows wm*32
    const int wn = w & 3;                  // 0..3 : cols wn*32
    const int g = lane >> 2, t2 = (lane & 3) * 2;

    const unsigned short* Ah = (const unsigned short*)(smc + SM_AHI);
    const unsigned short* Al = (const unsigned short*)(smc + SM_ALO);
    const unsigned short* Bh = (const unsigned short*)(smc + SM_BHI);
    const unsigned short* Bl = (const unsigned short*)(smc + SM_BLO);

    float acc[2][4][4];
    #pragma unroll
    for (int mt = 0; mt < 2; mt++)
        #pragma unroll
        for (int nt = 0; nt < 4; nt++)
            #pragma unroll
            for (int i = 0; i < 4; i++) acc[mt][nt][i] = 0.f;

    #pragma unroll
    for (int kk = 0; kk < 4; kk++) {
        const int k0 = kk * 16;
        uint32_t ah[2][4], al[2][4];
        #pragma unroll
        for (int mt = 0; mt < 2; mt++) {
            int r = wm * 32 + mt * 16 + g;
            ah[mt][0] = *(const uint32_t*)&Ah[(r    ) * 72 + k0 + t2];
            ah[mt][1] = *(const uint32_t*)&Ah[(r + 8) * 72 + k0 + t2];
            ah[mt][2] = *(const uint32_t*)&Ah[(r    ) * 72 + k0 + t2 + 8];
            ah[mt][3] = *(const uint32_t*)&Ah[(r + 8) * 72 + k0 + t2 + 8];
            al[mt][0] = *(const uint32_t*)&Al[(r    ) * 72 + k0 + t2];
            al[mt][1] = *(const uint32_t*)&Al[(r + 8) * 72 + k0 + t2];
            al[mt][2] = *(const uint32_t*)&Al[(r    ) * 72 + k0 + t2 + 8];
            al[mt][3] = *(const uint32_t*)&Al[(r + 8) * 72 + k0 + t2 + 8];
        }
        #pragma unroll
        for (int nt = 0; nt < 4; nt++) {
            int n = wn * 32 + nt * 8 + g;
            uint32_t bh0 = *(const uint32_t*)&Bh[n * 72 + k0 + t2];
            uint32_t bh1 = *(const uint32_t*)&Bh[n * 72 + k0 + t2 + 8];
            uint32_t bl0 = *(const uint32_t*)&Bl[n * 72 + k0 + t2];
            uint32_t bl1 = *(const uint32_t*)&Bl[n * 72 + k0 + t2 + 8];
            #pragma unroll
            for (int mt = 0; mt < 2; mt++) {
                mma_bf16(acc[mt][nt], ah[mt], bh0, bh1);
                mma_bf16(acc[mt][nt], ah[mt], bl0, bl1);
                mma_bf16(acc[mt][nt], al[mt], bh0, bh1);
            }
        }
    }
    __syncthreads();   // all A/B reads done before Es aliases the region

    // stage D + bias into Es: layout [edge][164], heads at h*20
    float* Es = (float*)(smc + SM_ES);
    #pragma unroll
    for (int mt = 0; mt < 2; mt++) {
        #pragma unroll
        for (int nt = 0; nt < 4; nt++) {
            int row = wm * 32 + mt * 16 + g;
            int col = wn * 32 + nt * 8 + t2;
            int h = col >> 4, d = col & 15;
            float b0 = sbe[col], b1 = sbe[col + 1];
            int i0 = row * ES_STRIDE + h * 20 + d;
            Es[i0]     = acc[mt][nt][0] + b0;
            Es[i0 + 1] = acc[mt][nt][1] + b1;
            int i1 = (row + 8) * ES_STRIDE + h * 20 + d;
            Es[i1]     = acc[mt][nt][2] + b0;
            Es[i1 + 1] = acc[mt][nt][3] + b1;
        }
    }
    __syncthreads();

    // -------- Phase B: 1024 items = 128 edges x 8 heads, 2 per thread --------
    #pragma unroll
    for (int it = 0; it < 2; it++) {
        int item = tid + it * 512;
        int le = item >> 3;
        int h  = item & 7;
        int e  = e0 + le;
        int src = ei[e];
        int dst = ei[N_EDGES + e];

        const float4* Kp = (const float4*)&g_K[(size_t)src * 64 + h * 8];
        const float4* Qp = (const float4*)&g_Q[(size_t)dst * 64 + h * 8];
        const float4* Vp = (const float4*)&g_V[(size_t)src * 64 + h * 8];
        float4 k0 = Kp[0], k1 = Kp[1];
        float4 q0 = Qp[0], q1 = Qp[1];
        float4 v0 = Vp[0], v1 = Vp[1];

        float t[8];
        t[0] = k0.x + q0.x; t[1] = k0.y + q0.y; t[2] = k0.z + q0.z; t[3] = k0.w + q0.w;
        t[4] = k1.x + q1.x; t[5] = k1.y + q1.y; t[6] = k1.z + q1.z; t[7] = k1.w + q1.w;

        const float* ep = &Es[le * ES_STRIDE + h * 20];
        float4 ew0 = *(const float4*)&ep[0];
        float4 ew1 = *(const float4*)&ep[4];
        float4 eb0 = *(const float4*)&ep[8];
        float4 eb1 = *(const float4*)&ep[12];
        float ew[8] = {ew0.x, ew0.y, ew0.z, ew0.w, ew1.x, ew1.y, ew1.z, ew1.w};
        float eb[8] = {eb0.x, eb0.y, eb0.z, eb0.w, eb1.x, eb1.y, eb1.z, eb1.w};

        float et[8];
        #pragma unroll
        for (int d = 0; d < 8; d++) {
            float u = t[d] * ew[d];
            float sc = copysignf(sqrt_approx(fabsf(u)), u) + eb[d];
            et[d] = fmaxf(sc, 0.f);
        }

        float4* wp = (float4*)&wE[(size_t)e * 64 + h * 8];
        wp[0] = make_float4(et[0], et[1], et[2], et[3]);
        wp[1] = make_float4(et[4], et[5], et[6], et[7]);

        float a = 0.f;
        #pragma unroll
        for (int d = 0; d < 8; d++) a = fmaf(et[d], sAw[d * 8 + h], a);
        a = fminf(fmaxf(a, -CLAMP_V), CLAMP_V);
        float p = __expf(a);

        atomicAdd(&g_s[(size_t)dst * 8 + h], p);
        float* wvp = &g_wV[(size_t)dst * 64 + h * 8];
        red_add_v4(wvp,     p * v0.x, p * v0.y, p * v0.z, p * v0.w);
        red_add_v4(wvp + 4, p * v1.x, p * v1.y, p * v1.z, p * v1.w);
        float* rwp = &g_row[(size_t)dst * 64 + h * 8];
        red_add_v4(rwp,     p * et[0], p * et[1], p * et[2], p * et[3]);
        red_add_v4(rwp + 4, p * et[4], p * et[5], p * et[6], p * et[7]);
    }
}

// ============================================================
// Kernel 3: finalize + self-zero scratch for next replay
// ============================================================
__global__ void finalize_kernel(const float* __restrict__ VeRow,
                                float* __restrict__ out) {
    __shared__ float Vr[512];
    const int tid = threadIdx.x;
    for (int i = tid; i < 512; i += 256) Vr[i] = VeRow[i];
    __syncthreads();

    int idx = blockIdx.x * 256 + tid;
    if (idx >= N_NODES * HEADS) return;
    int n = idx >> 3, h = idx & 7;

    float s = g_s[idx];
    g_s[idx] = 0.f;
    float inv = 1.f / (s + 1e-16f);

    float4* wp = (float4*)&g_wV[(size_t)n * 64 + h * 8];
    float4* rp = (float4*)&g_row[(size_t)n * 64 + h * 8];
    float4 w0 = wp[0], w1 = wp[1];
    float4 r0 = rp[0], r1 = rp[1];
    float4 z = make_float4(0.f, 0.f, 0.f, 0.f);
    wp[0] = z; wp[1] = z; rp[0] = z; rp[1] = z;

    float wv[8] = {w0.x, w0.y, w0.z, w0.w, w1.x, w1.y, w1.z, w1.w};
    float rv[8] = {r0.x, r0.y, r0.z, r0.w, r1.x, r1.y, r1.z, r1.w};

    float o[8];
    #pragma unroll
    for (int c = 0; c < 8; c++) o[c] = wv[c];
    #pragma unroll
    for (int d = 0; d < 8; d++) {
        float r = rv[d];
        #pragma unroll
        for (int c = 0; c < 8; c++)
            o[c] = fmaf(r, Vr[d * 64 + h * 8 + c], o[c]);
    }
    #pragma unroll
    for (int c = 0; c < 8; c++) o[c] *= inv;

    float4* op = (float4*)&out[(size_t)n * 64 + h * 8];
    op[0] = make_float4(o[0], o[1], o[2], o[3]);
    op[1] = make_float4(o[4], o[5], o[6], o[7]);
}

// ============================================================
extern "C" void kernel_launch(void* const* d_in, const int* in_sizes, int n_in,
                              void* d_out, int out_size) {
    const float* x    = (const float*)d_in[0];
    const float* ea   = (const float*)d_in[1];
    const int*   ei   = (const int*)  d_in[2];
    const float* Wq   = (const float*)d_in[3];
    const float* bq   = (const float*)d_in[4];
    const float* Wk   = (const float*)d_in[5];
    const float* bk   = (const float*)d_in[6];
    const float* We   = (const float*)d_in[7];
    const float* be   = (const float*)d_in[8];
    const float* Wv   = (const float*)d_in[9];
    const float* bv   = (const float*)d_in[10];
    const float* Aw   = (const float*)d_in[11];
    const float* VeRow= (const float*)d_in[12];

    float* out = (float*)d_out;                  // h_out: [N, 64]
    float* wE  = out + (size_t)N_NODES * 64;     // wE:    [E, 64]

    cudaFuncSetAttribute(qkv_mma_kernel, cudaFuncAttributeMaxDynamicSharedMemorySize, QB_TOTAL);
    cudaFuncSetAttribute(edge_kernel,    cudaFuncAttributeMaxDynamicSharedMemorySize, SM_TOTAL);

    prep_kernel<<<80, 256>>>(Wq, Wk, Wv, We);
    qkv_mma_kernel<<<(N_NODES + 127) / 128, 256, QB_TOTAL>>>(x, bq, bk, bv);
    edge_kernel<<<N_EDGES / 128, 512, SM_TOTAL>>>(ea, ei, be, Aw, wE);
    finalize_kernel<<<(N_NODES * HEADS + 255) / 256, 256>>>(VeRow, out);
}